// round 2
// baseline (speedup 1.0000x reference)
#include <cuda_runtime.h>

#define NNAT 16
#define MAX_TILES 200000

// Scratch (no allocs allowed): counters + reduction accumulators + folded params.
__device__ int   g_counts[MAX_TILES * NNAT];
// [0,64): sum tile_pos; [64,128): sum count_t*pte; [128,144): nation totals; [144,146): terrain counts
__device__ float g_acc[160];
__device__ float g_u[64];        // W_tile_top @ policy_w
__device__ float g_v[64];        // W_piece_bot @ policy_w
__device__ float g_q[16];        // (nation_emb @ W_piece_top) @ policy_w
__device__ float g_terrsc[2];    // (terrain_emb @ W_tile_bot) @ policy_w
__device__ float g_nproj[16 * 64];   // nation_emb @ W_piece_top
__device__ float g_tproj[2 * 64];    // terrain_emb @ W_tile_bot
__device__ float g_c0;           // (tile_fc_b + nation_emb[active]) . w + policy_b
__device__ float g_pbdot;        // piece_fc_b . w

// Zero all scratch with plain kernel stores — no memset nodes, no symbol-address
// API, nothing but kernel launches in the captured graph.
__global__ void k_zero(int n_counts)
{
    int i = blockIdx.x * blockDim.x + threadIdx.x;
    int stride = gridDim.x * blockDim.x;
    for (int k = i; k < n_counts; k += stride) g_counts[k] = 0;
    if (i < 160) g_acc[i] = 0.f;
}

__global__ void k_precompute(const float* __restrict__ tile_fc_w,
                             const float* __restrict__ tile_fc_b,
                             const float* __restrict__ piece_fc_w,
                             const float* __restrict__ piece_fc_b,
                             const float* __restrict__ tile_policy_w,
                             const float* __restrict__ tile_policy_b,
                             const float* __restrict__ nation_emb,
                             const float* __restrict__ terrain_emb,
                             const int*   __restrict__ active_nation)
{
    __shared__ float w[64];
    int j = threadIdx.x;  // 0..63
    w[j] = tile_policy_w[j];
    __syncthreads();

    // u[j] = sum_c tile_fc_w[j][c] * w[c]     (rows 0..63   = W_tile_top)
    // v[j] = sum_c piece_fc_w[64+j][c] * w[c] (rows 64..127 = W_piece_bot)
    float su = 0.f, sv = 0.f;
    for (int c = 0; c < 64; c++) {
        su += tile_fc_w[j * 64 + c] * w[c];
        sv += piece_fc_w[(64 + j) * 64 + c] * w[c];
    }
    g_u[j] = su;
    g_v[j] = sv;

    // nation_proj[n][j] = sum_k nation_emb[n][k] * piece_fc_w[k][j]
    for (int n = 0; n < 16; n++) {
        float s = 0.f;
        for (int k = 0; k < 64; k++)
            s += nation_emb[n * 64 + k] * piece_fc_w[k * 64 + j];
        g_nproj[n * 64 + j] = s;
    }
    // terr_proj[e][j] = sum_k terrain_emb[e][k] * tile_fc_w[64+k][j]
    for (int e = 0; e < 2; e++) {
        float s = 0.f;
        for (int k = 0; k < 64; k++)
            s += terrain_emb[e * 64 + k] * tile_fc_w[(64 + k) * 64 + j];
        g_tproj[e * 64 + j] = s;
    }
    __syncthreads();

    if (j < 16) {
        float s = 0.f;
        for (int c = 0; c < 64; c++) s += g_nproj[j * 64 + c] * w[c];
        g_q[j] = s;
    }
    if (j < 2) {
        float s = 0.f;
        for (int c = 0; c < 64; c++) s += g_tproj[j * 64 + c] * w[c];
        g_terrsc[j] = s;
    }
    if (j == 0) {
        int an = active_nation[0];
        float pb = 0.f, c0 = 0.f;
        for (int c = 0; c < 64; c++) {
            pb += piece_fc_b[c] * w[c];
            c0 += (tile_fc_b[c] + nation_emb[an * 64 + c]) * w[c];
        }
        g_pbdot = pb;
        g_c0 = c0 + tile_policy_b[0];
    }
}

__global__ void k_hist(const int* __restrict__ nation_idxs,
                       const int* __restrict__ piece_tile_idxs,
                       int P)
{
    int i = blockIdx.x * blockDim.x + threadIdx.x;
    if (i < P) {
        int t = piece_tile_idxs[i];
        int n = nation_idxs[i];
        atomicAdd(&g_counts[t * NNAT + n], 1);
    }
}

__global__ void k_tiles(const int*   __restrict__ tile_idxs,
                        const int*   __restrict__ terrain,
                        const float* __restrict__ tile_pos_emb,
                        const float* __restrict__ piece_tile_emb,
                        float*       __restrict__ out,
                        int T)
{
    int lane = threadIdx.x & 31;
    int wid  = (blockIdx.x * blockDim.x + threadIdx.x) >> 5;
    int nw   = (gridDim.x * blockDim.x) >> 5;

    float u0 = g_u[2 * lane], u1 = g_u[2 * lane + 1];
    float v0 = g_v[2 * lane], v1 = g_v[2 * lane + 1];
    float ql = (lane < 16) ? g_q[lane] : 0.f;

    float ap0 = 0.f, ap1 = 0.f;   // sum tile_pos (this lane's 2 dims)
    float ac0 = 0.f, ac1 = 0.f;   // sum count_t * pte
    float an  = 0.f;              // nation totals (lane<16)
    float t0  = 0.f, t1 = 0.f;    // terrain counts (lane 0)

    for (int t = wid; t < T; t += nw) {
        int row = tile_idxs[t];
        float2 tp = reinterpret_cast<const float2*>(tile_pos_emb)[row * 32 + lane];
        float2 pe = reinterpret_cast<const float2*>(piece_tile_emb)[t * 32 + lane];
        float  cf = (lane < 16) ? (float)g_counts[t * NNAT + lane] : 0.f;

        float s1 = tp.x * u0 + tp.y * u1 + cf * ql;  // pos-dot + nation-count-dot
        float s2 = pe.x * v0 + pe.y * v1;            // pte-dot
        float s3 = cf;                               // count_t
        #pragma unroll
        for (int o = 16; o > 0; o >>= 1) {
            s1 += __shfl_xor_sync(0xffffffffu, s1, o);
            s2 += __shfl_xor_sync(0xffffffffu, s2, o);
            s3 += __shfl_xor_sync(0xffffffffu, s3, o);
        }

        ap0 += tp.x; ap1 += tp.y;
        ac0 += s3 * pe.x; ac1 += s3 * pe.y;
        an  += cf;

        if (lane == 0) {
            int e = terrain[t] - 1;
            out[t] = s1 + g_terrsc[e] + s3 * (s2 + g_pbdot) + g_c0;
            if (e == 0) t0 += 1.f; else t1 += 1.f;
        }
    }

    atomicAdd(&g_acc[2 * lane],          ap0);
    atomicAdd(&g_acc[2 * lane + 1],      ap1);
    atomicAdd(&g_acc[64 + 2 * lane],     ac0);
    atomicAdd(&g_acc[64 + 2 * lane + 1], ac1);
    if (lane < 16) atomicAdd(&g_acc[128 + lane], an);
    if (lane == 0) {
        atomicAdd(&g_acc[144], t0);
        atomicAdd(&g_acc[145], t1);
    }
}

__global__ void k_final(const float* __restrict__ tile_fc_w,
                        const float* __restrict__ tile_fc_b,
                        const float* __restrict__ piece_fc_w,
                        const float* __restrict__ piece_fc_b,
                        const float* __restrict__ nation_emb,
                        const int*   __restrict__ active_nation,
                        const float* __restrict__ value_w1,
                        const float* __restrict__ value_b1,
                        const float* __restrict__ value_w2,
                        const float* __restrict__ value_b2,
                        const float* __restrict__ end_turn_logit,
                        float*       __restrict__ out,
                        int T, int P)
{
    __shared__ float pooled[64];
    __shared__ float h[64];
    int j = threadIdx.x;  // 0..63

    float s = 0.f;
    for (int k = 0; k < 64; k++) s += g_acc[k]      * tile_fc_w[k * 64 + j];
    for (int k = 0; k < 64; k++) s += g_acc[64 + k] * piece_fc_w[(64 + k) * 64 + j];
    for (int n = 0; n < 16; n++) s += g_acc[128 + n] * g_nproj[n * 64 + j];
    s += g_acc[144] * g_tproj[j] + g_acc[145] * g_tproj[64 + j];

    float fT = (float)T;
    int an = active_nation[0];
    s += fT * tile_fc_b[j] + (float)P * piece_fc_b[j] + fT * nation_emb[an * 64 + j];
    pooled[j] = s / fT;
    __syncthreads();

    float hv = value_b1[j];
    for (int k = 0; k < 64; k++) hv += pooled[k] * value_w1[k * 64 + j];
    h[j] = hv > 0.f ? hv : 0.f;
    __syncthreads();

    if (j == 0) {
        float v = value_b2[0];
        for (int k = 0; k < 64; k++) v += h[k] * value_w2[k];
        out[T]     = end_turn_logit[0];  // policy_logits[-1]
        out[T + 1] = v;                  // value
    }
}

extern "C" void kernel_launch(void* const* d_in, const int* in_sizes, int n_in,
                              void* d_out, int out_size)
{
    const int*   tile_idxs      = (const int*)  d_in[0];
    const int*   terrain        = (const int*)  d_in[1];
    const int*   nation_idxs    = (const int*)  d_in[2];
    const int*   piece_tidx     = (const int*)  d_in[3];
    const int*   active         = (const int*)  d_in[4];
    const float* tile_pos_emb   = (const float*)d_in[5];
    const float* terrain_emb    = (const float*)d_in[6];
    const float* nation_emb     = (const float*)d_in[7];
    const float* piece_tile_emb = (const float*)d_in[8];
    const float* tile_fc_w      = (const float*)d_in[9];
    const float* tile_fc_b      = (const float*)d_in[10];
    const float* piece_fc_w     = (const float*)d_in[11];
    const float* piece_fc_b     = (const float*)d_in[12];
    const float* tile_policy_w  = (const float*)d_in[13];
    const float* tile_policy_b  = (const float*)d_in[14];
    const float* end_turn       = (const float*)d_in[15];
    const float* value_w1       = (const float*)d_in[16];
    const float* value_b1       = (const float*)d_in[17];
    const float* value_w2       = (const float*)d_in[18];
    const float* value_b2       = (const float*)d_in[19];
    float* out = (float*)d_out;

    int T = in_sizes[0];   // 200000
    int P = in_sizes[2];   // 1000000

    k_zero<<<592, 256>>>(T * NNAT);

    k_precompute<<<1, 64>>>(tile_fc_w, tile_fc_b, piece_fc_w, piece_fc_b,
                            tile_policy_w, tile_policy_b, nation_emb, terrain_emb,
                            active);

    k_hist<<<(P + 255) / 256, 256>>>(nation_idxs, piece_tidx, P);

    k_tiles<<<592, 256>>>(tile_idxs, terrain, tile_pos_emb, piece_tile_emb, out, T);

    k_final<<<1, 64>>>(tile_fc_w, tile_fc_b, piece_fc_w, piece_fc_b,
                       nation_emb, active,
                       value_w1, value_b1, value_w2, value_b2,
                       end_turn, out, T, P);
}

// round 3
// speedup vs baseline: 1.5100x; 1.5100x over previous
#include <cuda_runtime.h>

#define NNAT 16
#define MAX_TILES 200000

// Scratch (no allocs allowed): counters + reduction accumulators + folded params.
__device__ int   g_counts[MAX_TILES * NNAT];
// [0,64): sum tile_pos; [64,128): sum count_t*pte; [128,144): nation totals; [144,146): terrain counts
__device__ float g_acc[160];
__device__ float g_u[64];        // W_tile_top @ policy_w
__device__ float g_v[64];        // W_piece_bot @ policy_w
__device__ float g_q[16];        // (nation_emb @ W_piece_top) @ policy_w
__device__ float g_terrsc[2];    // (terrain_emb @ W_tile_bot) @ policy_w
__device__ float g_nproj[16 * 64];   // nation_emb @ W_piece_top
__device__ float g_tproj[2 * 64];    // terrain_emb @ W_tile_bot
__device__ float g_c0;           // (tile_fc_b + nation_emb[active]) . w + policy_b
__device__ float g_pbdot;        // piece_fc_b . w

// Fused: blocks 0..591 zero the scratch; block 592 does the parameter folding
// with 256 parallel threads (the old 1-block/64-thread version serialized ~1000
// dependent global loads on one SM).
__global__ void k_zero_pre(int n_counts,
                           const float* __restrict__ tile_fc_w,
                           const float* __restrict__ tile_fc_b,
                           const float* __restrict__ piece_fc_w,
                           const float* __restrict__ piece_fc_b,
                           const float* __restrict__ tile_policy_w,
                           const float* __restrict__ tile_policy_b,
                           const float* __restrict__ nation_emb,
                           const float* __restrict__ terrain_emb,
                           const int*   __restrict__ active_nation)
{
    if (blockIdx.x < 592) {
        int i = blockIdx.x * blockDim.x + threadIdx.x;
        int stride = 592 * blockDim.x;
        for (int k = i; k < n_counts; k += stride) g_counts[k] = 0;
        if (i < 160) g_acc[i] = 0.f;
        return;
    }

    // ---- precompute block (256 threads) ----
    __shared__ float w[64];
    int tid = threadIdx.x;
    if (tid < 64) w[tid] = tile_policy_w[tid];
    __syncthreads();

    // nproj[n][j] (1024 outputs): 4 per thread
    #pragma unroll
    for (int r = 0; r < 4; r++) {
        int idx = tid + 256 * r;        // 0..1023
        int n = idx >> 6, j = idx & 63;
        float s = 0.f;
        for (int k = 0; k < 64; k++)
            s += nation_emb[n * 64 + k] * piece_fc_w[k * 64 + j];
        g_nproj[idx] = s;
    }

    if (tid < 64) {
        // u[j] = tile_fc_w[j,:] . w   (rows 0..63 = W_tile_top)
        float s = 0.f;
        for (int c = 0; c < 64; c++) s += tile_fc_w[tid * 64 + c] * w[c];
        g_u[tid] = s;
    } else if (tid < 128) {
        // v[j] = piece_fc_w[64+j,:] . w (rows 64..127 = W_piece_bot)
        int j = tid - 64;
        float s = 0.f;
        for (int c = 0; c < 64; c++) s += piece_fc_w[(64 + j) * 64 + c] * w[c];
        g_v[j] = s;
    } else {
        // tproj[e][j] = terrain_emb[e,:] @ tile_fc_w[64:,:]  (128 outputs)
        int idx = tid - 128;            // 0..127
        int e = idx >> 6, j = idx & 63;
        float s = 0.f;
        for (int k = 0; k < 64; k++)
            s += terrain_emb[e * 64 + k] * tile_fc_w[(64 + k) * 64 + j];
        g_tproj[idx] = s;
    }
    __syncthreads();  // global writes by this block visible to this block

    if (tid < 16) {
        float s = 0.f;
        for (int c = 0; c < 64; c++) s += g_nproj[tid * 64 + c] * w[c];
        g_q[tid] = s;
    } else if (tid < 18) {
        int e = tid - 16;
        float s = 0.f;
        for (int c = 0; c < 64; c++) s += g_tproj[e * 64 + c] * w[c];
        g_terrsc[e] = s;
    } else if (tid == 18) {
        float s = 0.f;
        for (int c = 0; c < 64; c++) s += piece_fc_b[c] * w[c];
        g_pbdot = s;
    } else if (tid == 19) {
        int an = active_nation[0];
        float s = 0.f;
        for (int c = 0; c < 64; c++)
            s += (tile_fc_b[c] + nation_emb[an * 64 + c]) * w[c];
        g_c0 = s + tile_policy_b[0];
    }
}

__global__ void k_hist(const int* __restrict__ nation_idxs,
                       const int* __restrict__ piece_tile_idxs,
                       int P)
{
    int i = blockIdx.x * blockDim.x + threadIdx.x;
    if (i < P) {
        int t = piece_tile_idxs[i];
        int n = nation_idxs[i];
        atomicAdd(&g_counts[t * NNAT + n], 1);
    }
}

__global__ void k_tiles(const int*   __restrict__ tile_idxs,
                        const int*   __restrict__ terrain,
                        const float* __restrict__ tile_pos_emb,
                        const float* __restrict__ piece_tile_emb,
                        float*       __restrict__ out,
                        int T)
{
    const int U = 4;
    int lane = threadIdx.x & 31;
    int gwid = (blockIdx.x * blockDim.x + threadIdx.x) >> 5;
    int nw   = (gridDim.x * blockDim.x) >> 5;

    float u0 = g_u[2 * lane], u1 = g_u[2 * lane + 1];
    float v0 = g_v[2 * lane], v1 = g_v[2 * lane + 1];
    float ql = (lane < 16) ? g_q[lane] : 0.f;
    float pb = g_pbdot, c0 = g_c0;
    float tsc0 = g_terrsc[0], tsc1 = g_terrsc[1];

    float ap0 = 0.f, ap1 = 0.f;   // sum tile_pos (this lane's 2 dims)
    float ac0 = 0.f, ac1 = 0.f;   // sum count_t * pte
    float an  = 0.f;              // nation totals (lane<16)
    float tc0 = 0.f, tc1 = 0.f;   // terrain counts (lane 0)

    const float2* __restrict__ tp_base = reinterpret_cast<const float2*>(tile_pos_emb);
    const float2* __restrict__ pe_base = reinterpret_cast<const float2*>(piece_tile_emb);

    for (int base = gwid * U; base < T; base += nw * U) {
        float2 tp[U], pe[U];
        float  cf[U];
        bool   val[U];

        // Batched independent loads — MLP across the 4 tiles.
        #pragma unroll
        for (int i = 0; i < U; i++) {
            int t = base + i;
            val[i] = (t < T);
            int tt = val[i] ? t : base;
            int row = tile_idxs[tt];
            tp[i] = tp_base[row * 32 + lane];
            pe[i] = pe_base[tt * 32 + lane];
            cf[i] = (lane < 16) ? (float)g_counts[tt * NNAT + lane] : 0.f;
        }
        #pragma unroll
        for (int i = 0; i < U; i++) {
            if (!val[i]) { tp[i].x = tp[i].y = 0.f; pe[i].x = pe[i].y = 0.f; cf[i] = 0.f; }
        }

        float s1[U], s2[U], s3[U];
        #pragma unroll
        for (int i = 0; i < U; i++) {
            s1[i] = tp[i].x * u0 + tp[i].y * u1 + cf[i] * ql;
            s2[i] = pe[i].x * v0 + pe[i].y * v1;
            s3[i] = cf[i];
        }

        // 12 independent shuffles per level — pipelined, chain amortized x4.
        #pragma unroll
        for (int o = 16; o > 0; o >>= 1) {
            #pragma unroll
            for (int i = 0; i < U; i++) {
                s1[i] += __shfl_xor_sync(0xffffffffu, s1[i], o);
                s2[i] += __shfl_xor_sync(0xffffffffu, s2[i], o);
                s3[i] += __shfl_xor_sync(0xffffffffu, s3[i], o);
            }
        }

        #pragma unroll
        for (int i = 0; i < U; i++) {
            ap0 += tp[i].x;        ap1 += tp[i].y;
            ac0 += s3[i] * pe[i].x; ac1 += s3[i] * pe[i].y;
            an  += cf[i];
        }

        if (lane == 0) {
            #pragma unroll
            for (int i = 0; i < U; i++) {
                if (val[i]) {
                    int e = terrain[base + i] - 1;
                    out[base + i] = s1[i] + (e == 0 ? tsc0 : tsc1)
                                  + s3[i] * (s2[i] + pb) + c0;
                    if (e == 0) tc0 += 1.f; else tc1 += 1.f;
                }
            }
        }
    }

    atomicAdd(&g_acc[2 * lane],          ap0);
    atomicAdd(&g_acc[2 * lane + 1],      ap1);
    atomicAdd(&g_acc[64 + 2 * lane],     ac0);
    atomicAdd(&g_acc[64 + 2 * lane + 1], ac1);
    if (lane < 16) atomicAdd(&g_acc[128 + lane], an);
    if (lane == 0) {
        atomicAdd(&g_acc[144], tc0);
        atomicAdd(&g_acc[145], tc1);
    }
}

__global__ void k_final(const float* __restrict__ tile_fc_w,
                        const float* __restrict__ tile_fc_b,
                        const float* __restrict__ piece_fc_w,
                        const float* __restrict__ piece_fc_b,
                        const float* __restrict__ nation_emb,
                        const int*   __restrict__ active_nation,
                        const float* __restrict__ value_w1,
                        const float* __restrict__ value_b1,
                        const float* __restrict__ value_w2,
                        const float* __restrict__ value_b2,
                        const float* __restrict__ end_turn_logit,
                        float*       __restrict__ out,
                        int T, int P)
{
    __shared__ float pooled[64];
    __shared__ float h[64];
    int j = threadIdx.x;  // 0..63

    float s = 0.f;
    for (int k = 0; k < 64; k++) s += g_acc[k]      * tile_fc_w[k * 64 + j];
    for (int k = 0; k < 64; k++) s += g_acc[64 + k] * piece_fc_w[(64 + k) * 64 + j];
    for (int n = 0; n < 16; n++) s += g_acc[128 + n] * g_nproj[n * 64 + j];
    s += g_acc[144] * g_tproj[j] + g_acc[145] * g_tproj[64 + j];

    float fT = (float)T;
    int an = active_nation[0];
    s += fT * tile_fc_b[j] + (float)P * piece_fc_b[j] + fT * nation_emb[an * 64 + j];
    pooled[j] = s / fT;
    __syncthreads();

    float hv = value_b1[j];
    for (int k = 0; k < 64; k++) hv += pooled[k] * value_w1[k * 64 + j];
    h[j] = hv > 0.f ? hv : 0.f;
    __syncthreads();

    if (j == 0) {
        float v = value_b2[0];
        for (int k = 0; k < 64; k++) v += h[k] * value_w2[k];
        out[T]     = end_turn_logit[0];  // policy_logits[-1]
        out[T + 1] = v;                  // value
    }
}

extern "C" void kernel_launch(void* const* d_in, const int* in_sizes, int n_in,
                              void* d_out, int out_size)
{
    const int*   tile_idxs      = (const int*)  d_in[0];
    const int*   terrain        = (const int*)  d_in[1];
    const int*   nation_idxs    = (const int*)  d_in[2];
    const int*   piece_tidx     = (const int*)  d_in[3];
    const int*   active         = (const int*)  d_in[4];
    const float* tile_pos_emb   = (const float*)d_in[5];
    const float* terrain_emb    = (const float*)d_in[6];
    const float* nation_emb     = (const float*)d_in[7];
    const float* piece_tile_emb = (const float*)d_in[8];
    const float* tile_fc_w      = (const float*)d_in[9];
    const float* tile_fc_b      = (const float*)d_in[10];
    const float* piece_fc_w     = (const float*)d_in[11];
    const float* piece_fc_b     = (const float*)d_in[12];
    const float* tile_policy_w  = (const float*)d_in[13];
    const float* tile_policy_b  = (const float*)d_in[14];
    const float* end_turn       = (const float*)d_in[15];
    const float* value_w1       = (const float*)d_in[16];
    const float* value_b1       = (const float*)d_in[17];
    const float* value_w2       = (const float*)d_in[18];
    const float* value_b2       = (const float*)d_in[19];
    float* out = (float*)d_out;

    int T = in_sizes[0];   // 200000
    int P = in_sizes[2];   // 1000000

    k_zero_pre<<<593, 256>>>(T * NNAT,
                             tile_fc_w, tile_fc_b, piece_fc_w, piece_fc_b,
                             tile_policy_w, tile_policy_b, nation_emb, terrain_emb,
                             active);

    k_hist<<<(P + 255) / 256, 256>>>(nation_idxs, piece_tidx, P);

    k_tiles<<<592, 256>>>(tile_idxs, terrain, tile_pos_emb, piece_tile_emb, out, T);

    k_final<<<1, 64>>>(tile_fc_w, tile_fc_b, piece_fc_w, piece_fc_b,
                       nation_emb, active,
                       value_w1, value_b1, value_w2, value_b2,
                       end_turn, out, T, P);
}